// round 3
// baseline (speedup 1.0000x reference)
#include <cuda_runtime.h>
#include <cstdint>

#define N_NODES 50000
#define D 128
#define N_EDGES 800000
#define L_LAYERS 3

// Scratch (allocation-free requirement -> __device__ globals)
__device__ float g_h0[(size_t)N_NODES * D];
__device__ float g_h1[(size_t)N_NODES * D];
__device__ float g_agg[(size_t)N_NODES * D];

// ---------------------------------------------------------------------------
// zero: grid-stride float4 clear
// ---------------------------------------------------------------------------
__global__ void zero_kernel(float* __restrict__ p, int n4) {
    float4 z = make_float4(0.f, 0.f, 0.f, 0.f);
    for (int i = blockIdx.x * blockDim.x + threadIdx.x; i < n4;
         i += gridDim.x * blockDim.x)
        reinterpret_cast<float4*>(p)[i] = z;
}

// ---------------------------------------------------------------------------
// scatter: agg[dst[e]] += h[src[e]]   (one warp per edge, float4 lanes,
// vectorized L2 reduction red.global.add.v4.f32)
// ---------------------------------------------------------------------------
__global__ void scatter_kernel(const float* __restrict__ h,
                               const int* __restrict__ edge_index,
                               float* __restrict__ agg) {
    const int* __restrict__ src = edge_index;
    const int* __restrict__ dst = edge_index + N_EDGES;
    int lane = threadIdx.x & 31;
    int warp = (blockIdx.x * blockDim.x + threadIdx.x) >> 5;
    int nwarps = (gridDim.x * blockDim.x) >> 5;
    for (int e = warp; e < N_EDGES; e += nwarps) {
        int s = __ldg(src + e);
        int d = __ldg(dst + e);
        float4 v = __ldg(reinterpret_cast<const float4*>(h + (size_t)s * D) + lane);
        float* ap = agg + (size_t)d * D + lane * 4;
        asm volatile("red.global.add.v4.f32 [%0], {%1,%2,%3,%4};"
                     :: "l"(ap), "f"(v.x), "f"(v.y), "f"(v.z), "f"(v.w)
                     : "memory");
    }
}

// ---------------------------------------------------------------------------
// SGEMM: in_fc   out[N,128] = x[N,128] @ W[128,128] + bias
// BM=128, BN=128, BK=16, 256 threads, 8x8 per thread
// ---------------------------------------------------------------------------
__global__ __launch_bounds__(256) void gemm_infc(const float* __restrict__ A,
                                                 const float* __restrict__ W,
                                                 const float* __restrict__ bias,
                                                 float* __restrict__ out) {
    __shared__ float As[16][132];  // [k][row], padded
    __shared__ float Ws[16][128];  // [k][col]
    int t = threadIdx.x;
    int tx = t & 15, ty = t >> 4;
    int blockRow = blockIdx.x * 128;
    float acc[8][8] = {};

    for (int kk = 0; kk < 128; kk += 16) {
        // A tile: rows blockRow..+128, cols kk..kk+16 (transpose into As)
#pragma unroll
        for (int it = 0; it < 2; it++) {
            int idx = t + it * 256;            // 512 float4 = 2048 floats
            int r   = idx >> 2;                // 0..127
            int c4  = (idx & 3) * 4;           // 0,4,8,12
            int row = blockRow + r;
            float4 v = make_float4(0.f, 0.f, 0.f, 0.f);
            if (row < N_NODES)
                v = *reinterpret_cast<const float4*>(A + (size_t)row * D + kk + c4);
            As[c4 + 0][r] = v.x;
            As[c4 + 1][r] = v.y;
            As[c4 + 2][r] = v.z;
            As[c4 + 3][r] = v.w;
        }
        // W tile: rows kk..kk+16, cols 0..128
#pragma unroll
        for (int it = 0; it < 2; it++) {
            int idx = t + it * 256;
            int r   = idx >> 5;                // 0..15
            int c4  = (idx & 31) * 4;
            *reinterpret_cast<float4*>(&Ws[r][c4]) =
                *reinterpret_cast<const float4*>(W + (size_t)(kk + r) * D + c4);
        }
        __syncthreads();
#pragma unroll
        for (int k = 0; k < 16; k++) {
            float a[8], b[8];
            *reinterpret_cast<float4*>(&a[0]) = *reinterpret_cast<const float4*>(&As[k][ty * 8 + 0]);
            *reinterpret_cast<float4*>(&a[4]) = *reinterpret_cast<const float4*>(&As[k][ty * 8 + 4]);
            *reinterpret_cast<float4*>(&b[0]) = *reinterpret_cast<const float4*>(&Ws[k][tx * 8 + 0]);
            *reinterpret_cast<float4*>(&b[4]) = *reinterpret_cast<const float4*>(&Ws[k][tx * 8 + 4]);
#pragma unroll
            for (int i = 0; i < 8; i++)
#pragma unroll
                for (int j = 0; j < 8; j++) acc[i][j] += a[i] * b[j];
        }
        __syncthreads();
    }
#pragma unroll
    for (int i = 0; i < 8; i++) {
        int row = blockRow + ty * 8 + i;
        if (row >= N_NODES) break;
#pragma unroll
        for (int j = 0; j < 8; j++) {
            int col = tx * 8 + j;
            out[(size_t)row * D + col] = acc[i][j] + __ldg(bias + col);
        }
    }
}

// ---------------------------------------------------------------------------
// Fused layer GEMM:  out = relu([agg|h] @ [Wr;Wroot] + b) + h       (K = 256)
// ---------------------------------------------------------------------------
__global__ __launch_bounds__(256) void gemm_layer(const float* __restrict__ Agg,
                                                  const float* __restrict__ H,
                                                  const float* __restrict__ Wr,
                                                  const float* __restrict__ Wroot,
                                                  const float* __restrict__ bias,
                                                  float* __restrict__ out) {
    __shared__ float As[16][132];
    __shared__ float Ws[16][128];
    int t = threadIdx.x;
    int tx = t & 15, ty = t >> 4;
    int blockRow = blockIdx.x * 128;
    float acc[8][8] = {};

    for (int kk = 0; kk < 256; kk += 16) {
        const float* __restrict__ Asrc = (kk < 128) ? Agg : H;
        const float* __restrict__ Wsrc = (kk < 128) ? Wr : Wroot;
        int kbase = kk & 127;
#pragma unroll
        for (int it = 0; it < 2; it++) {
            int idx = t + it * 256;
            int r   = idx >> 2;
            int c4  = (idx & 3) * 4;
            int row = blockRow + r;
            float4 v = make_float4(0.f, 0.f, 0.f, 0.f);
            if (row < N_NODES)
                v = *reinterpret_cast<const float4*>(Asrc + (size_t)row * D + kbase + c4);
            As[c4 + 0][r] = v.x;
            As[c4 + 1][r] = v.y;
            As[c4 + 2][r] = v.z;
            As[c4 + 3][r] = v.w;
        }
#pragma unroll
        for (int it = 0; it < 2; it++) {
            int idx = t + it * 256;
            int r   = idx >> 5;
            int c4  = (idx & 31) * 4;
            *reinterpret_cast<float4*>(&Ws[r][c4]) =
                *reinterpret_cast<const float4*>(Wsrc + (size_t)(kbase + r) * D + c4);
        }
        __syncthreads();
#pragma unroll
        for (int k = 0; k < 16; k++) {
            float a[8], b[8];
            *reinterpret_cast<float4*>(&a[0]) = *reinterpret_cast<const float4*>(&As[k][ty * 8 + 0]);
            *reinterpret_cast<float4*>(&a[4]) = *reinterpret_cast<const float4*>(&As[k][ty * 8 + 4]);
            *reinterpret_cast<float4*>(&b[0]) = *reinterpret_cast<const float4*>(&Ws[k][tx * 8 + 0]);
            *reinterpret_cast<float4*>(&b[4]) = *reinterpret_cast<const float4*>(&Ws[k][tx * 8 + 4]);
#pragma unroll
            for (int i = 0; i < 8; i++)
#pragma unroll
                for (int j = 0; j < 8; j++) acc[i][j] += a[i] * b[j];
        }
        __syncthreads();
    }
#pragma unroll
    for (int i = 0; i < 8; i++) {
        int row = blockRow + ty * 8 + i;
        if (row >= N_NODES) break;
#pragma unroll
        for (int j = 0; j < 8; j++) {
            int col = tx * 8 + j;
            float v = acc[i][j] + __ldg(bias + col);
            v = fmaxf(v, 0.f) + __ldg(H + (size_t)row * D + col);
            out[(size_t)row * D + col] = v;
        }
    }
}

// ---------------------------------------------------------------------------
extern "C" void kernel_launch(void* const* d_in, const int* in_sizes, int n_in,
                              void* d_out, int out_size) {
    const float* x      = (const float*)d_in[0];
    const int*   ei     = (const int*)d_in[1];
    const float* win    = (const float*)d_in[2];
    const float* bin    = (const float*)d_in[3];
    const float* w_rel  = (const float*)d_in[4];
    const float* b_rel  = (const float*)d_in[5];
    const float* w_root = (const float*)d_in[6];
    float* out = (float*)d_out;

    float *h0, *h1, *agg;
    cudaGetSymbolAddress((void**)&h0, g_h0);
    cudaGetSymbolAddress((void**)&h1, g_h1);
    cudaGetSymbolAddress((void**)&agg, g_agg);

    const int gemm_grid = (N_NODES + 127) / 128;  // 391
    const int n4 = N_NODES * D / 4;

    // h0 = x @ Win + b
    gemm_infc<<<gemm_grid, 256>>>(x, win, bin, h0);

    float* hin  = h0;
    float* hout = h1;
    for (int l = 0; l < L_LAYERS; l++) {
        float* dst = (l == L_LAYERS - 1) ? out : hout;
        zero_kernel<<<1024, 256>>>(agg, n4);
        scatter_kernel<<<4096, 256>>>(hin, ei, agg);
        gemm_layer<<<gemm_grid, 256>>>(agg, hin,
                                       w_rel + (size_t)l * D * D,
                                       w_root + (size_t)l * D * D,
                                       b_rel + (size_t)l * D,
                                       dst);
        float* tmp = hin; hin = dst; hout = tmp;
    }
}

// round 6
// speedup vs baseline: 1.0594x; 1.0594x over previous
#include <cuda_runtime.h>
#include <cstdint>

#define N_NODES 50000
#define D 128
#define N_EDGES 800000
#define L_LAYERS 3

// Scratch (allocation-free requirement -> __device__ globals)
__device__ float g_h0[(size_t)N_NODES * D];
__device__ float g_h1[(size_t)N_NODES * D];
__device__ float g_agg[(size_t)N_NODES * D];

// ---------------------------------------------------------------------------
// packed fp32x2 helpers (sm_103a: FFMA2 only reachable via PTX fma.rn.f32x2)
// ---------------------------------------------------------------------------
__device__ __forceinline__ void fma2(unsigned long long& acc,
                                     unsigned long long a,
                                     unsigned long long b) {
    asm("fma.rn.f32x2 %0, %1, %2, %3;" : "=l"(acc) : "l"(a), "l"(b), "l"(acc));
}
__device__ __forceinline__ unsigned long long bcast2(float x) {
    unsigned long long r;
    asm("mov.b64 %0, {%1, %1};" : "=l"(r) : "f"(x));
    return r;
}
__device__ __forceinline__ float2 unpack2(unsigned long long v) {
    float2 r;
    asm("mov.b64 {%0, %1}, %2;" : "=f"(r.x), "=f"(r.y) : "l"(v));
    return r;
}

// ---------------------------------------------------------------------------
// zero: grid-stride float4 clear
// ---------------------------------------------------------------------------
__global__ void zero_kernel(float* __restrict__ p, int n4) {
    float4 z = make_float4(0.f, 0.f, 0.f, 0.f);
    for (int i = blockIdx.x * blockDim.x + threadIdx.x; i < n4;
         i += gridDim.x * blockDim.x)
        reinterpret_cast<float4*>(p)[i] = z;
}

// ---------------------------------------------------------------------------
// scatter: agg[dst[e]] += h[src[e]]   (one warp per edge, float4 lanes,
// vectorized L2 reduction red.global.add.v4.f32). Unrolled x4 for MLP.
// ---------------------------------------------------------------------------
__global__ void scatter_kernel(const float* __restrict__ h,
                               const int* __restrict__ edge_index,
                               float* __restrict__ agg) {
    const int* __restrict__ src = edge_index;
    const int* __restrict__ dst = edge_index + N_EDGES;
    int lane = threadIdx.x & 31;
    int warp = (blockIdx.x * blockDim.x + threadIdx.x) >> 5;
    int nwarps = (gridDim.x * blockDim.x) >> 5;
    int e = warp;
    for (; e + 3 * nwarps < N_EDGES; e += 4 * nwarps) {
        int e0 = e, e1 = e + nwarps, e2 = e + 2 * nwarps, e3 = e + 3 * nwarps;
        int s0 = __ldg(src + e0), d0 = __ldg(dst + e0);
        int s1 = __ldg(src + e1), d1 = __ldg(dst + e1);
        int s2 = __ldg(src + e2), d2 = __ldg(dst + e2);
        int s3 = __ldg(src + e3), d3 = __ldg(dst + e3);
        float4 v0 = __ldg(reinterpret_cast<const float4*>(h + (size_t)s0 * D) + lane);
        float4 v1 = __ldg(reinterpret_cast<const float4*>(h + (size_t)s1 * D) + lane);
        float4 v2 = __ldg(reinterpret_cast<const float4*>(h + (size_t)s2 * D) + lane);
        float4 v3 = __ldg(reinterpret_cast<const float4*>(h + (size_t)s3 * D) + lane);
        asm volatile("red.global.add.v4.f32 [%0], {%1,%2,%3,%4};"
                     :: "l"(agg + (size_t)d0 * D + lane * 4),
                        "f"(v0.x), "f"(v0.y), "f"(v0.z), "f"(v0.w) : "memory");
        asm volatile("red.global.add.v4.f32 [%0], {%1,%2,%3,%4};"
                     :: "l"(agg + (size_t)d1 * D + lane * 4),
                        "f"(v1.x), "f"(v1.y), "f"(v1.z), "f"(v1.w) : "memory");
        asm volatile("red.global.add.v4.f32 [%0], {%1,%2,%3,%4};"
                     :: "l"(agg + (size_t)d2 * D + lane * 4),
                        "f"(v2.x), "f"(v2.y), "f"(v2.z), "f"(v2.w) : "memory");
        asm volatile("red.global.add.v4.f32 [%0], {%1,%2,%3,%4};"
                     :: "l"(agg + (size_t)d3 * D + lane * 4),
                        "f"(v3.x), "f"(v3.y), "f"(v3.z), "f"(v3.w) : "memory");
    }
    for (; e < N_EDGES; e += nwarps) {
        int s = __ldg(src + e);
        int d = __ldg(dst + e);
        float4 v = __ldg(reinterpret_cast<const float4*>(h + (size_t)s * D) + lane);
        asm volatile("red.global.add.v4.f32 [%0], {%1,%2,%3,%4};"
                     :: "l"(agg + (size_t)d * D + lane * 4),
                        "f"(v.x), "f"(v.y), "f"(v.z), "f"(v.w) : "memory");
    }
}

// ---------------------------------------------------------------------------
// Shared GEMM core: BM=128, BN=128, BK=16, 256 threads, 8x8 per thread,
// inner product via packed fma.rn.f32x2 (2 FMA per issue slot).
// acc2[i][p] holds cols (tx*8 + 2p, tx*8 + 2p + 1) for row (ty*8 + i).
// ---------------------------------------------------------------------------
struct AccTile {
    unsigned long long a[8][4];
};

__device__ __forceinline__ void gemm_ktile(const float (*As)[132],
                                           const float (*Ws)[128],
                                           int tx, int ty, AccTile& acc) {
#pragma unroll
    for (int k = 0; k < 16; k++) {
        float a[8];
        *reinterpret_cast<float4*>(&a[0]) = *reinterpret_cast<const float4*>(&As[k][ty * 8 + 0]);
        *reinterpret_cast<float4*>(&a[4]) = *reinterpret_cast<const float4*>(&As[k][ty * 8 + 4]);
        ulonglong2 b01 = *reinterpret_cast<const ulonglong2*>(&Ws[k][tx * 8 + 0]);
        ulonglong2 b23 = *reinterpret_cast<const ulonglong2*>(&Ws[k][tx * 8 + 4]);
        unsigned long long aa[8];
#pragma unroll
        for (int i = 0; i < 8; i++) aa[i] = bcast2(a[i]);
#pragma unroll
        for (int i = 0; i < 8; i++) {
            fma2(acc.a[i][0], aa[i], b01.x);
            fma2(acc.a[i][1], aa[i], b01.y);
            fma2(acc.a[i][2], aa[i], b23.x);
            fma2(acc.a[i][3], aa[i], b23.y);
        }
    }
}

__device__ __forceinline__ void load_A_tile(const float* __restrict__ Asrc,
                                            int blockRow, int kbase, int t,
                                            float (*As)[132]) {
#pragma unroll
    for (int it = 0; it < 2; it++) {
        int idx = t + it * 256;            // 512 float4 = 2048 floats
        int r   = idx >> 2;                // 0..127
        int c4  = (idx & 3) * 4;           // 0,4,8,12
        int row = blockRow + r;
        float4 v = make_float4(0.f, 0.f, 0.f, 0.f);
        if (row < N_NODES)
            v = *reinterpret_cast<const float4*>(Asrc + (size_t)row * D + kbase + c4);
        As[c4 + 0][r] = v.x;
        As[c4 + 1][r] = v.y;
        As[c4 + 2][r] = v.z;
        As[c4 + 3][r] = v.w;
    }
}

__device__ __forceinline__ void load_W_tile(const float* __restrict__ Wsrc,
                                            int kbase, int t, float (*Ws)[128]) {
#pragma unroll
    for (int it = 0; it < 2; it++) {
        int idx = t + it * 256;
        int r   = idx >> 5;                // 0..15
        int c4  = (idx & 31) * 4;
        *reinterpret_cast<float4*>(&Ws[r][c4]) =
            *reinterpret_cast<const float4*>(Wsrc + (size_t)(kbase + r) * D + c4);
    }
}

// ---------------------------------------------------------------------------
// SGEMM: in_fc   out[N,128] = x[N,128] @ W[128,128] + bias
// ---------------------------------------------------------------------------
__global__ __launch_bounds__(256) void gemm_infc(const float* __restrict__ A,
                                                 const float* __restrict__ W,
                                                 const float* __restrict__ bias,
                                                 float* __restrict__ out) {
    __shared__ float As[16][132];
    __shared__ float Ws[16][128];
    int t = threadIdx.x;
    int tx = t & 15, ty = t >> 4;
    int blockRow = blockIdx.x * 128;
    AccTile acc = {};

    for (int kk = 0; kk < 128; kk += 16) {
        load_A_tile(A, blockRow, kk, t, As);
        load_W_tile(W, kk, t, Ws);
        __syncthreads();
        gemm_ktile(As, Ws, tx, ty, acc);
        __syncthreads();
    }
#pragma unroll
    for (int i = 0; i < 8; i++) {
        int row = blockRow + ty * 8 + i;
        if (row >= N_NODES) break;
#pragma unroll
        for (int p = 0; p < 4; p++) {
            int col = tx * 8 + p * 2;
            float2 v = unpack2(acc.a[i][p]);
            out[(size_t)row * D + col + 0] = v.x + __ldg(bias + col + 0);
            out[(size_t)row * D + col + 1] = v.y + __ldg(bias + col + 1);
        }
    }
}

// ---------------------------------------------------------------------------
// Fused layer GEMM:  out = relu([agg|h] @ [Wr;Wroot] + b) + h       (K = 256)
// ---------------------------------------------------------------------------
__global__ __launch_bounds__(256) void gemm_layer(const float* __restrict__ Agg,
                                                  const float* __restrict__ H,
                                                  const float* __restrict__ Wr,
                                                  const float* __restrict__ Wroot,
                                                  const float* __restrict__ bias,
                                                  float* __restrict__ out) {
    __shared__ float As[16][132];
    __shared__ float Ws[16][128];
    int t = threadIdx.x;
    int tx = t & 15, ty = t >> 4;
    int blockRow = blockIdx.x * 128;
    AccTile acc = {};

    for (int kk = 0; kk < 256; kk += 16) {
        const float* __restrict__ Asrc = (kk < 128) ? Agg : H;
        const float* __restrict__ Wsrc = (kk < 128) ? Wr : Wroot;
        int kbase = kk & 127;
        load_A_tile(Asrc, blockRow, kbase, t, As);
        load_W_tile(Wsrc, kbase, t, Ws);
        __syncthreads();
        gemm_ktile(As, Ws, tx, ty, acc);
        __syncthreads();
    }
#pragma unroll
    for (int i = 0; i < 8; i++) {
        int row = blockRow + ty * 8 + i;
        if (row >= N_NODES) break;
#pragma unroll
        for (int p = 0; p < 4; p++) {
            int col = tx * 8 + p * 2;
            float2 v = unpack2(acc.a[i][p]);
            float o0 = fmaxf(v.x + __ldg(bias + col + 0), 0.f) + H[(size_t)row * D + col + 0];
            float o1 = fmaxf(v.y + __ldg(bias + col + 1), 0.f) + H[(size_t)row * D + col + 1];
            out[(size_t)row * D + col + 0] = o0;
            out[(size_t)row * D + col + 1] = o1;
        }
    }
}

// ---------------------------------------------------------------------------
extern "C" void kernel_launch(void* const* d_in, const int* in_sizes, int n_in,
                              void* d_out, int out_size) {
    const float* x      = (const float*)d_in[0];
    const int*   ei     = (const int*)d_in[1];
    const float* win    = (const float*)d_in[2];
    const float* bin    = (const float*)d_in[3];
    const float* w_rel  = (const float*)d_in[4];
    const float* b_rel  = (const float*)d_in[5];
    const float* w_root = (const float*)d_in[6];
    float* out = (float*)d_out;

    float *h0, *h1, *agg;
    cudaGetSymbolAddress((void**)&h0, g_h0);
    cudaGetSymbolAddress((void**)&h1, g_h1);
    cudaGetSymbolAddress((void**)&agg, g_agg);

    const int gemm_grid = (N_NODES + 127) / 128;  // 391
    const int n4 = N_NODES * D / 4;

    // h0 = x @ Win + b
    gemm_infc<<<gemm_grid, 256>>>(x, win, bin, h0);

    float* hin  = h0;
    float* hout = h1;
    for (int l = 0; l < L_LAYERS; l++) {
        float* dst = (l == L_LAYERS - 1) ? out : hout;
        zero_kernel<<<1024, 256>>>(agg, n4);
        scatter_kernel<<<4096, 256>>>(hin, ei, agg);
        gemm_layer<<<gemm_grid, 256>>>(agg, hin,
                                       w_rel + (size_t)l * D * D,
                                       w_root + (size_t)l * D * D,
                                       b_rel + (size_t)l * D,
                                       dst);
        float* tmp = hin; hin = dst; hout = tmp;
    }
}